// round 2
// baseline (speedup 1.0000x reference)
#include <cuda_runtime.h>
#include <cstdint>

// Problem constants
#define N_IMG   32
#define C_IN    256
#define H_DIM   56
#define W_DIM   56
#define HW      (H_DIM * W_DIM)        // 3136
#define OCH     256
#define KTOT    (C_IN * 9)             // 2304
#define M_TOT   (N_IMG * HW)           // 100352

// GEMM tiling
#define BM 128
#define BN 128
#define BK 16
#define NTHREADS 256
#define KSTEPS (KTOT / BK)             // 144

// Dequantized + transposed weights: Wt[k][o], k = c*9 + kh*3 + kw
__device__ float d_Wt[KTOT * OCH];

// ---------------------------------------------------------------------------
// Prep: dequantize q[o][k] -> Wt[k][o]  (w = q*scale + min folded in)
// ---------------------------------------------------------------------------
__global__ void qc_dequant_kernel(const int* __restrict__ q,
                                  const float* __restrict__ scale,
                                  const float* __restrict__ wmin) {
    int idx = blockIdx.x * blockDim.x + threadIdx.x;
    if (idx >= KTOT * OCH) return;
    int o = idx / KTOT;
    int k = idx - o * KTOT;            // q is [O][K] contiguous in k -> coalesced read
    float s = *scale;
    float mn = *wmin;
    d_Wt[k * OCH + o] = (float)q[idx] * s + mn;
}

// ---------------------------------------------------------------------------
// Main: implicit-GEMM conv, fp32 with packed fma.rn.f32x2
//   out[m, o] = sum_k A[m,k] * Wt[k,o] + bias[o]
//   A[m,k] = x[n, c, h+kh-1, w+kw-1] (0 outside), m=(n,h,w), k=(c,kh,kw)
// ---------------------------------------------------------------------------
__global__ __launch_bounds__(NTHREADS, 2)
void qc_conv_gemm_kernel(const float* __restrict__ x,
                         const float* __restrict__ bias,
                         float* __restrict__ out) {
    __shared__ float sA[2][BK][BM];    // [k][m] layout
    __shared__ float sB[2][BK][BN];    // [k][o] layout

    const int tid = threadIdx.x;
    const int bm = blockIdx.x;         // 784 tiles over M
    const int bn = blockIdx.y;         // 2 tiles over O

    // ---- A (im2col gather) load mapping: thread covers 1 m, 8 k's ----
    const int a_m  = tid & 127;
    const int a_k0 = (tid >> 7) << 3;              // 0 or 8
    const int m    = bm * BM + a_m;
    const int n_i  = m / HW;
    const int hw   = m - n_i * HW;
    const int h    = hw / W_DIM;
    const int w    = hw - h * W_DIM;
    // base pointer at (n, c=0, h-1, w-1); deref always guarded by predicate
    const float* xb = x + (size_t)n_i * C_IN * HW + (h - 1) * W_DIM + (w - 1);

    // ---- compute mapping: 16 x 16 threads, 8x8 outputs each ----
    const int tx = tid & 15;           // O direction
    const int ty = tid >> 4;           // M direction

    float  regA[8];
    float4 regB0, regB1;

    unsigned long long acc[8][4];      // 8 m-rows x 4 packed o-pairs (= 8 o cols)
#pragma unroll
    for (int i = 0; i < 8; i++)
#pragma unroll
        for (int j = 0; j < 4; j++) acc[i][j] = 0ULL;

    // ---------------- helpers ----------------
    auto loadA = [&](int kt) {
#pragma unroll
        for (int i = 0; i < 8; i++) {
            int k  = kt * BK + a_k0 + i;
            int c  = k / 9;
            int r  = k - c * 9;
            int kh = r / 3;
            int kw = r - kh * 3;
            bool ok = ((unsigned)(h + kh - 1) < H_DIM) && ((unsigned)(w + kw - 1) < W_DIM);
            regA[i] = ok ? xb[c * HW + kh * W_DIM + kw] : 0.0f;
        }
    };
    auto loadB = [&](int kt) {
        const float4* p = reinterpret_cast<const float4*>(d_Wt + (size_t)kt * BK * OCH + bn * BN);
        // row stride in float4 = OCH/4 = 64; 32 float4 per 128-wide slice row
        regB0 = p[(tid >> 5) * (OCH / 4) + (tid & 31)];
        int e1 = tid + 256;
        regB1 = p[(e1 >> 5) * (OCH / 4) + (e1 & 31)];
    };
    auto storeTiles = [&](int buf) {
#pragma unroll
        for (int i = 0; i < 8; i++) sA[buf][a_k0 + i][a_m] = regA[i];
        *reinterpret_cast<float4*>(&sB[buf][tid >> 5][(tid & 31) * 4]) = regB0;
        int e1 = tid + 256;
        *reinterpret_cast<float4*>(&sB[buf][e1 >> 5][(e1 & 31) * 4]) = regB1;
    };
    auto compute = [&](int buf) {
#pragma unroll
        for (int kk = 0; kk < BK; kk++) {
            float4 a0 = *reinterpret_cast<const float4*>(&sA[buf][kk][ty * 8]);
            float4 a1 = *reinterpret_cast<const float4*>(&sA[buf][kk][ty * 8 + 4]);
            float af[8] = {a0.x, a0.y, a0.z, a0.w, a1.x, a1.y, a1.z, a1.w};
            const unsigned long long* bp =
                reinterpret_cast<const unsigned long long*>(&sB[buf][kk][tx * 8]);
            unsigned long long b0 = bp[0], b1 = bp[1], b2 = bp[2], b3 = bp[3];
#pragma unroll
            for (int i = 0; i < 8; i++) {
                unsigned long long a2;
                asm("mov.b64 %0, {%1, %1};" : "=l"(a2) : "f"(af[i]));
                asm("fma.rn.f32x2 %0, %1, %2, %0;" : "+l"(acc[i][0]) : "l"(a2), "l"(b0));
                asm("fma.rn.f32x2 %0, %1, %2, %0;" : "+l"(acc[i][1]) : "l"(a2), "l"(b1));
                asm("fma.rn.f32x2 %0, %1, %2, %0;" : "+l"(acc[i][2]) : "l"(a2), "l"(b2));
                asm("fma.rn.f32x2 %0, %1, %2, %0;" : "+l"(acc[i][3]) : "l"(a2), "l"(b3));
            }
        }
    };

    // ---------------- mainloop: register-staged double buffer ----------------
    loadA(0); loadB(0);
    storeTiles(0);
    __syncthreads();

    int buf = 0;
    for (int kt = 0; kt < KSTEPS; kt++) {
        if (kt + 1 < KSTEPS) { loadA(kt + 1); loadB(kt + 1); }
        compute(buf);
        if (kt + 1 < KSTEPS) {
            storeTiles(buf ^ 1);       // safe: buf^1 last read before previous barrier
            __syncthreads();
            buf ^= 1;
        }
    }

    // ---------------- epilogue ----------------
    const int obase = bn * BN + tx * 8;
#pragma unroll
    for (int i = 0; i < 8; i++) {
        int mo  = bm * BM + ty * 8 + i;
        int n2  = mo / HW;
        int hw2 = mo - n2 * HW;
        float* op = out + (size_t)n2 * OCH * HW + hw2;
#pragma unroll
        for (int j = 0; j < 4; j++) {
            float lo, hi;
            asm("mov.b64 {%0, %1}, %2;" : "=f"(lo), "=f"(hi) : "l"(acc[i][j]));
            int o0 = obase + 2 * j;
            op[(size_t)o0 * HW]       = lo + __ldg(&bias[o0]);
            op[(size_t)(o0 + 1) * HW] = hi + __ldg(&bias[o0 + 1]);
        }
    }
}

// ---------------------------------------------------------------------------
// Launch. Inputs (metadata order): x, q_weight, w_scale, w_min, bias
// ---------------------------------------------------------------------------
extern "C" void kernel_launch(void* const* d_in, const int* in_sizes, int n_in,
                              void* d_out, int out_size) {
    const float* x      = (const float*)d_in[0];
    const int*   q      = (const int*)  d_in[1];
    const float* wscale = (const float*)d_in[2];
    const float* wmin   = (const float*)d_in[3];
    const float* bias   = (const float*)d_in[4];
    float*       out    = (float*)d_out;

    // 1) dequantize + transpose weights
    {
        int total = KTOT * OCH;
        qc_dequant_kernel<<<(total + 255) / 256, 256>>>(q, wscale, wmin);
    }

    // 2) implicit GEMM conv
    {
        dim3 grid(M_TOT / BM, OCH / BN);   // (784, 2)
        qc_conv_gemm_kernel<<<grid, NTHREADS>>>(x, bias, out);
    }
}

// round 4
// speedup vs baseline: 5.5057x; 5.5057x over previous
#include <cuda_runtime.h>
#include <cuda_fp16.h>
#include <cstdint>

// ---------------- problem constants ----------------
#define C_IN   256
#define HDIM   56
#define WDIM   56
#define HW     3136
#define OCH    256
#define KTOT   2304               // reordered: k' = tap*256 + c
#define M_TOT  100352

// ---------------- GEMM config ----------------
#define BM     128
#define BN     128
#define BK     32
#define NTHREADS 256
#define KCH    (KTOT / BK)        // 72 chunks; 8 chunks per tap
#define ASTRIDE 40                // halves per smem row (padded; conflict-free)

// ---------------- device scratch ----------------
__device__ __align__(16) __half d_Wq[OCH * KTOT];   // [o][tap*256+c], exact fp16 of q
__device__ float d_S[M_TOT];                        // per-position channel sums
__device__ float d_R[M_TOT];                        // 3x3 window sums of d_S

// ---------------- helpers ----------------
__device__ __forceinline__ uint32_t smem_u32(const void* p) {
    uint32_t a;
    asm("{ .reg .u64 t; cvta.to.shared.u64 t, %1; cvt.u32.u64 %0, t; }" : "=r"(a) : "l"(p));
    return a;
}
__device__ __forceinline__ void ldmatrix_x4(uint32_t& r0, uint32_t& r1, uint32_t& r2,
                                            uint32_t& r3, uint32_t addr) {
    asm volatile("ldmatrix.sync.aligned.m8n8.x4.shared.b16 {%0,%1,%2,%3}, [%4];"
                 : "=r"(r0), "=r"(r1), "=r"(r2), "=r"(r3) : "r"(addr));
}
__device__ __forceinline__ void mma16816(float* c, uint32_t a0, uint32_t a1, uint32_t a2,
                                         uint32_t a3, uint32_t b0, uint32_t b1) {
    asm volatile(
        "mma.sync.aligned.m16n8k16.row.col.f32.f16.f16.f32 "
        "{%0,%1,%2,%3}, {%4,%5,%6,%7}, {%8,%9}, {%0,%1,%2,%3};"
        : "+f"(c[0]), "+f"(c[1]), "+f"(c[2]), "+f"(c[3])
        : "r"(a0), "r"(a1), "r"(a2), "r"(a3), "r"(b0), "r"(b1));
}
__device__ __forceinline__ void cp_async16(uint32_t saddr, const void* gaddr) {
    asm volatile("cp.async.cg.shared.global [%0], [%1], 16;" :: "r"(saddr), "l"(gaddr));
}

// ---------------- prep kernels ----------------
__global__ void qc_wprep(const int* __restrict__ q) {
    int idx = blockIdx.x * blockDim.x + threadIdx.x;
    if (idx >= OCH * KTOT) return;
    int o   = idx / KTOT;
    int ks  = idx - o * KTOT;          // source k = c*9 + tap
    int c   = ks / 9;
    int tap = ks - c * 9;
    d_Wq[o * KTOT + tap * 256 + c] = __int2half_rn(q[idx]);   // exact (0..255)
}

__global__ void qc_ssum(const float* __restrict__ x) {
    int m = blockIdx.x * blockDim.x + threadIdx.x;
    if (m >= M_TOT) return;
    int n  = m / HW;
    int hw = m - n * HW;
    const float* p = x + (size_t)n * C_IN * HW + hw;
    float s = 0.f;
#pragma unroll 8
    for (int c = 0; c < C_IN; c++) s += p[(size_t)c * HW];
    d_S[m] = s;
}

__global__ void qc_rsum() {
    int m = blockIdx.x * blockDim.x + threadIdx.x;
    if (m >= M_TOT) return;
    int n  = m / HW;
    int hw = m - n * HW;
    int h  = hw / WDIM;
    int w  = hw - h * WDIM;
    const float* base = d_S + (size_t)n * HW;
    float acc = 0.f;
#pragma unroll
    for (int kh = 0; kh < 3; kh++)
#pragma unroll
        for (int kw = 0; kw < 3; kw++) {
            int hh = h + kh - 1, ww = w + kw - 1;
            if ((unsigned)hh < HDIM && (unsigned)ww < WDIM)
                acc += base[hh * WDIM + ww];
        }
    d_R[m] = acc;
}

// ---------------- main fp16 mma.sync implicit-GEMM kernel ----------------
__global__ __launch_bounds__(NTHREADS, 2)
void qc_mma_kernel(const float* __restrict__ x,
                   const float* __restrict__ wscale,
                   const float* __restrict__ wmin,
                   const float* __restrict__ bias,
                   float* __restrict__ out) {
    __shared__ __half sA[2][BM * ASTRIDE];
    __shared__ __half sB[2][BN * ASTRIDE];

    const int tid  = threadIdx.x;
    const int lane = tid & 31;
    const int wid  = tid >> 5;
    const int bm   = blockIdx.x;
    const int bn   = blockIdx.y;

    // ---- A producer mapping: thread covers row m=tid&127, k-half khalf ----
    const int am    = tid & 127;
    const int khalf = tid >> 7;              // 0 or 1 (16 k's each)
    const int m     = bm * BM + am;
    const int n_i   = m / HW;
    const int hw    = m - n_i * HW;
    const int h     = hw / WDIM;
    const int w     = hw - h * WDIM;

    // ---- B producer mapping: 2 cp.async of 16B per thread ----
    const int brow = tid >> 1;               // 0..127
    const int bseg = (tid & 1) * 2;          // 0 or 2 (+1 inside)
    const __half* bsrc0 = d_Wq + (size_t)(bn * BN + brow) * KTOT + bseg * 8;
    const uint32_t sB0 = smem_u32(&sB[0][0]);
    const uint32_t sA0 = smem_u32(&sA[0][0]);
    const uint32_t bdst0 = sB0 + brow * (ASTRIDE * 2) + bseg * 16;

    // ---- compute mapping: 8 warps as 2(M) x 4(N), each 64x32 ----
    const int warp_m = wid >> 2;
    const int warp_n = wid & 3;

    // ldmatrix lane address components (byte offsets within a stage)
    // A tile (mt, ks): row = warp_m*64 + mt*16 + (lane&15); col = ks*16 + (lane>>4)*8
    uint32_t aoff[4];
#pragma unroll
    for (int mt = 0; mt < 4; mt++) {
        int row = warp_m * 64 + mt * 16 + (lane & 15);
        int col = (lane >> 4) * 8;
        aoff[mt] = (uint32_t)(row * ASTRIDE + col) * 2;
    }
    // B tile pair (nt2, ks): row = warp_n*32 + nt2*16 + ((lane>>4)<<3) + (lane&7);
    //                        col = ((lane>>3)&1)*8 + ks*16
    uint32_t boff[2];
#pragma unroll
    for (int nt2 = 0; nt2 < 2; nt2++) {
        int row = warp_n * 32 + nt2 * 16 + ((lane >> 4) << 3) + (lane & 7);
        int col = ((lane >> 3) & 1) * 8;
        boff[nt2] = (uint32_t)(row * ASTRIDE + col) * 2;
    }

    float acc[4][4][4];
#pragma unroll
    for (int i = 0; i < 4; i++)
#pragma unroll
        for (int j = 0; j < 4; j++)
#pragma unroll
            for (int r = 0; r < 4; r++) acc[i][j][r] = 0.f;

    uint32_t apk[8];   // staged A (8 x half2)

    // ---- helpers (lambdas) ----
    auto loadA = [&](int kt) {
        const int tap = kt >> 3;
        const int kh  = tap / 3;
        const int kw  = tap - 3 * kh;
        const int hh  = h + kh - 1, ww = w + kw - 1;
        const bool pred = ((unsigned)hh < HDIM) && ((unsigned)ww < WDIM);
        const int cbase = (kt & 7) * 32 + khalf * 16;
        const float* p = x + ((size_t)n_i * C_IN + cbase) * HW + hh * WDIM + ww;
#pragma unroll
        for (int i = 0; i < 8; i++) {
            float f0 = pred ? p[(size_t)(2 * i) * HW]     : 0.f;
            float f1 = pred ? p[(size_t)(2 * i + 1) * HW] : 0.f;
            __half2 h2 = __floats2half2_rn(f0, f1);
            apk[i] = *reinterpret_cast<uint32_t*>(&h2);
        }
    };
    auto stsA = [&](int st) {
        uint32_t dst = sA0 + st * (BM * ASTRIDE * 2) + (am * ASTRIDE + khalf * 16) * 2;
        asm volatile("st.shared.v4.b32 [%0], {%1,%2,%3,%4};"
                     :: "r"(dst), "r"(apk[0]), "r"(apk[1]), "r"(apk[2]), "r"(apk[3]));
        asm volatile("st.shared.v4.b32 [%0], {%1,%2,%3,%4};"
                     :: "r"(dst + 16), "r"(apk[4]), "r"(apk[5]), "r"(apk[6]), "r"(apk[7]));
    };
    auto cpB = [&](int kt, int st) {
        const __half* g = bsrc0 + kt * BK;
        uint32_t d = bdst0 + st * (BN * ASTRIDE * 2);
        cp_async16(d, g);
        cp_async16(d + 16, g + 8);
        asm volatile("cp.async.commit_group;");
    };
    auto compute = [&](int st) {
        const uint32_t aS = sA0 + st * (BM * ASTRIDE * 2);
        const uint32_t bS = sB0 + st * (BN * ASTRIDE * 2);
#pragma unroll
        for (int ks = 0; ks < 2; ks++) {
            uint32_t a[4][4], b[2][4];
#pragma unroll
            for (int mt = 0; mt < 4; mt++)
                ldmatrix_x4(a[mt][0], a[mt][1], a[mt][2], a[mt][3],
                            aS + aoff[mt] + ks * 32);
#pragma unroll
            for (int nt2 = 0; nt2 < 2; nt2++)
                ldmatrix_x4(b[nt2][0], b[nt2][1], b[nt2][2], b[nt2][3],
                            bS + boff[nt2] + ks * 32);
#pragma unroll
            for (int mt = 0; mt < 4; mt++) {
#pragma unroll
                for (int nt = 0; nt < 4; nt++) {
                    uint32_t b0 = b[nt >> 1][(nt & 1) * 2];
                    uint32_t b1 = b[nt >> 1][(nt & 1) * 2 + 1];
                    mma16816(acc[mt][nt], a[mt][0], a[mt][1], a[mt][2], a[mt][3], b0, b1);
                }
            }
        }
    };

    // ---- mainloop ----
    loadA(0);
    cpB(0, 0);
    stsA(0);
    asm volatile("cp.async.wait_group 0;" ::: "memory");
    __syncthreads();

    int cur = 0;
    for (int kt = 0; kt < KCH; kt++) {
        if (kt + 1 < KCH) {
            loadA(kt + 1);
            cpB(kt + 1, cur ^ 1);
        }
        compute(cur);
        if (kt + 1 < KCH) {
            stsA(cur ^ 1);
            asm volatile("cp.async.wait_group 0;" ::: "memory");
            __syncthreads();
            cur ^= 1;
        }
    }

    // ---- epilogue: out = s*acc + mn*R[m] + bias[o] ----
    const float s  = __ldg(wscale);
    const float mn = __ldg(wmin);
    const int g  = lane >> 2;
    const int qd = (lane & 3) * 2;
#pragma unroll
    for (int mt = 0; mt < 4; mt++) {
#pragma unroll
        for (int hh2 = 0; hh2 < 2; hh2++) {
            const int mloc = warp_m * 64 + mt * 16 + g + 8 * hh2;
            const int mo   = bm * BM + mloc;
            const int n2   = mo / HW;
            const int hw2  = mo - n2 * HW;
            const float bm_ = mn * d_R[mo];
            float* op = out + (size_t)n2 * OCH * HW + hw2;
#pragma unroll
            for (int nt = 0; nt < 4; nt++) {
                const int o0 = bn * BN + warp_n * 32 + nt * 8 + qd;
                op[(size_t)o0 * HW] =
                    fmaf(s, acc[mt][nt][hh2 * 2],     bm_ + __ldg(&bias[o0]));
                op[(size_t)(o0 + 1) * HW] =
                    fmaf(s, acc[mt][nt][hh2 * 2 + 1], bm_ + __ldg(&bias[o0 + 1]));
            }
        }
    }
}

// ---------------- launch ----------------
extern "C" void kernel_launch(void* const* d_in, const int* in_sizes, int n_in,
                              void* d_out, int out_size) {
    const float* x      = (const float*)d_in[0];
    const int*   q      = (const int*)  d_in[1];
    const float* wscale = (const float*)d_in[2];
    const float* wmin   = (const float*)d_in[3];
    const float* bias   = (const float*)d_in[4];
    float*       out    = (float*)d_out;

    qc_wprep<<<(OCH * KTOT + 255) / 256, 256>>>(q);
    qc_ssum<<<(M_TOT + 255) / 256, 256>>>(x);
    qc_rsum<<<(M_TOT + 255) / 256, 256>>>();

    dim3 grid(M_TOT / BM, OCH / BN);     // (784, 2)
    qc_mma_kernel<<<grid, NTHREADS>>>(x, wscale, wmin, bias, out);
}